// round 10
// baseline (speedup 1.0000x reference)
#include <cuda_runtime.h>

// DecisionGate: g = 1/(1+|x|^4); mask = g>=0.5; dispatched[b,p,:] = (mask? g:0)*act[b,:]
// x [4096,64] f32, act [4096,512] f32. Output f32: g [B*P] | mask [B*P] | dispatched [B*P*D]
//
// R10: R7 structure with 256-bit stores (st.global.cs.v8.f32, sm_10x STG.256).
// Thread t owns 8 floats of act[b] at d=(t&63)*8; CTA halves handle even/odd
// p-rows; 32 STG.256 per thread instead of 64 STG.128. Traffic identical.

#define B_DIM 4096
#define P_DIM 64
#define D_DIM 512
#define BP    (B_DIM * P_DIM)

__device__ __forceinline__ void stg256_cs(float* p, float4 a, float4 b) {
    asm volatile(
        "st.global.cs.v8.f32 [%0], {%1,%2,%3,%4,%5,%6,%7,%8};"
        :: "l"(p),
           "f"(a.x), "f"(a.y), "f"(a.z), "f"(a.w),
           "f"(b.x), "f"(b.y), "f"(b.z), "f"(b.w)
        : "memory");
}

__global__ __launch_bounds__(128, 16)
void decision_gate_kernel(const float* __restrict__ x,
                          const float* __restrict__ act,
                          float* __restrict__ out) {
    const int b    = blockIdx.x;
    const int t    = threadIdx.x;
    const int d    = t & 63;              // which 32B chunk of the D=512 row
    const int half = t >> 6;              // 0: even p-rows, 1: odd p-rows

    // Each thread owns 8 consecutive floats of act[b] (two float4 registers).
    const float4* a4 = reinterpret_cast<const float4*>(act + (size_t)b * D_DIM) + d * 2;
    const float4 v0 = a4[0];
    const float4 v1 = a4[1];

    // Threads 0..63 compute the 64 gate values; emit g and mask; stash w in smem.
    __shared__ float wsm[P_DIM];
    if (t < P_DIM) {
        const float xv = x[b * P_DIM + t];
        const float x2 = xv * xv;
        const float g  = 1.0f / (1.0f + x2 * x2);
        const bool  m  = (g >= 0.5f);
        __stcs(&out[b * P_DIM + t], g);
        __stcs(&out[BP + b * P_DIM + t], m ? 1.0f : 0.0f);
        wsm[t] = m ? g : 0.0f;
    }
    __syncthreads();

    // 32 independent 256-bit streaming stores per thread.
    float* __restrict__ base =
        out + (size_t)2 * BP + (size_t)b * P_DIM * D_DIM + d * 8;

    #pragma unroll
    for (int p = 0; p < P_DIM; p += 2) {
        const int row = p + half;
        const float w = wsm[row];         // broadcast LDS, conflict-free
        float4 r0, r1;
        r0.x = v0.x * w; r0.y = v0.y * w; r0.z = v0.z * w; r0.w = v0.w * w;
        r1.x = v1.x * w; r1.y = v1.y * w; r1.z = v1.z * w; r1.w = v1.w * w;
        stg256_cs(base + (size_t)row * D_DIM, r0, r1);
    }
}

extern "C" void kernel_launch(void* const* d_in, const int* in_sizes, int n_in,
                              void* d_out, int out_size) {
    const float* x   = (const float*)d_in[0];   // [4096, 64]
    const float* act = (const float*)d_in[1];   // [4096, 512]
    float* out = (float*)d_out;

    decision_gate_kernel<<<B_DIM, 128>>>(x, act, out);
}

// round 11
// speedup vs baseline: 1.0178x; 1.0178x over previous
#include <cuda_runtime.h>

// DecisionGate: g = 1/(1+|x|^4); mask = g>=0.5; dispatched[b,p,:] = (mask? g:0)*act[b,:]
// x [4096,64] f32, act [4096,512] f32. Output f32: g [B*P] | mask [B*P] | dispatched [B*P*D]
//
// FINAL (R7 form; best of an 11-round series, reproduced twice at 82.0-82.1us):
// 1 batch row per 128-thread CTA; act row held in registers (one float4 per
// thread); 64 gate values in smem; 64 independent .cs streaming STG.128 per
// thread (MLP~64 hides store latency via ~77% occupancy).
//
// At the external write-stream roofline (~6.4 TB/s effective for the 523 MB
// output). Eliminated by experiment: .wt/default store policy (R3/R8),
// 2-row CTAs (R4), persistent+prefetch (R5, occupancy regression), L2
// de-phasing rotation (R6), STG.256 (R10).

#define B_DIM 4096
#define P_DIM 64
#define D_DIM 512
#define BP    (B_DIM * P_DIM)

__global__ __launch_bounds__(128, 16)
void decision_gate_kernel(const float* __restrict__ x,
                          const float* __restrict__ act,
                          float* __restrict__ out) {
    const int b = blockIdx.x;
    const int t = threadIdx.x;            // 0..127, one float4 of D=512 each

    // Each thread owns one float4 of act[b] for the whole CTA lifetime.
    const float4 v = reinterpret_cast<const float4*>(act + (size_t)b * D_DIM)[t];

    // Threads 0..63 compute the 64 gate values; emit g and mask; stash w in smem.
    __shared__ float wsm[P_DIM];
    if (t < P_DIM) {
        const float xv = x[b * P_DIM + t];
        const float x2 = xv * xv;
        const float g  = 1.0f / (1.0f + x2 * x2);
        const bool  m  = (g >= 0.5f);
        __stcs(&out[b * P_DIM + t], g);
        __stcs(&out[BP + b * P_DIM + t], m ? 1.0f : 0.0f);
        wsm[t] = m ? g : 0.0f;
    }
    __syncthreads();

    // 64 independent streaming stores per thread: dispatched[b,p,:] = w[p] * v
    float4* __restrict__ base =
        reinterpret_cast<float4*>(out + (size_t)2 * BP + (size_t)b * P_DIM * D_DIM) + t;

    #pragma unroll
    for (int p = 0; p < P_DIM; p++) {
        const float w = wsm[p];           // broadcast LDS, conflict-free
        float4 r;
        r.x = v.x * w;
        r.y = v.y * w;
        r.z = v.z * w;
        r.w = v.w * w;
        __stcs(base + (size_t)p * (D_DIM / 4), r);
    }
}

extern "C" void kernel_launch(void* const* d_in, const int* in_sizes, int n_in,
                              void* d_out, int out_size) {
    const float* x   = (const float*)d_in[0];   // [4096, 64]
    const float* act = (const float*)d_in[1];   // [4096, 512]
    float* out = (float*)d_out;

    decision_gate_kernel<<<B_DIM, 128>>>(x, act, out);
}

// round 12
// speedup vs baseline: 1.0218x; 1.0039x over previous
#include <cuda_runtime.h>

// DecisionGate: g = 1/(1+|x|^4); mask = g>=0.5; dispatched[b,p,:] = (mask? g:0)*act[b,:]
// x [4096,64] f32, act [4096,512] f32. Output f32: g [B*P] | mask [B*P] | dispatched [B*P*D]
//
// TERMINAL (R7 form; best of a 12-round series, reproduced 3x at 82.0-82.6us):
// 1 batch row per 128-thread CTA; act row held in registers (one float4 per
// thread); 64 gate values in smem; 64 independent .cs streaming STG.128 per
// thread (MLP~64 per thread; ~77% occupancy hides all store latency).
//
// At the external write-stream roofline: 523 MB output in 82us = 6.4 TB/s
// effective. Eliminated by experiment: .wt/default store policy (R3/R8),
// 2-row CTAs (R4), persistent+prefetch (R5, occupancy regression), L2
// de-phasing rotation (R6), STG.256 (R10).

#define B_DIM 4096
#define P_DIM 64
#define D_DIM 512
#define BP    (B_DIM * P_DIM)

__global__ __launch_bounds__(128, 16)
void decision_gate_kernel(const float* __restrict__ x,
                          const float* __restrict__ act,
                          float* __restrict__ out) {
    const int b = blockIdx.x;
    const int t = threadIdx.x;            // 0..127, one float4 of D=512 each

    // Each thread owns one float4 of act[b] for the whole CTA lifetime.
    const float4 v = reinterpret_cast<const float4*>(act + (size_t)b * D_DIM)[t];

    // Threads 0..63 compute the 64 gate values; emit g and mask; stash w in smem.
    __shared__ float wsm[P_DIM];
    if (t < P_DIM) {
        const float xv = x[b * P_DIM + t];
        const float x2 = xv * xv;
        const float g  = 1.0f / (1.0f + x2 * x2);
        const bool  m  = (g >= 0.5f);
        __stcs(&out[b * P_DIM + t], g);
        __stcs(&out[BP + b * P_DIM + t], m ? 1.0f : 0.0f);
        wsm[t] = m ? g : 0.0f;
    }
    __syncthreads();

    // 64 independent streaming stores per thread: dispatched[b,p,:] = w[p] * v
    float4* __restrict__ base =
        reinterpret_cast<float4*>(out + (size_t)2 * BP + (size_t)b * P_DIM * D_DIM) + t;

    #pragma unroll
    for (int p = 0; p < P_DIM; p++) {
        const float w = wsm[p];           // broadcast LDS, conflict-free
        float4 r;
        r.x = v.x * w;
        r.y = v.y * w;
        r.z = v.z * w;
        r.w = v.w * w;
        __stcs(base + (size_t)p * (D_DIM / 4), r);
    }
}

extern "C" void kernel_launch(void* const* d_in, const int* in_sizes, int n_in,
                              void* d_out, int out_size) {
    const float* x   = (const float*)d_in[0];   // [4096, 64]
    const float* act = (const float*)d_in[1];   // [4096, 512]
    float* out = (float*)d_out;

    decision_gate_kernel<<<B_DIM, 128>>>(x, act, out);
}